// round 15
// baseline (speedup 1.0000x reference)
#include <cuda_runtime.h>
#include <cuda_fp16.h>
#include <math.h>
#include <stdint.h>

#define BATCH 64
#define SEQ   512
#define EMB   256
#define HID   512
#define G4    2048   // 4*HID
#define NCLS  4
#define NCTA  128    // persistent CTAs: 64 j-groups x 2 batch-halves
#define UNITS 8      // hidden units per j-group
#define HPAD  68     // fp32 pad stride (xg_gemm)
#define PS    36     // pre row stride (32 + 4)

// Scratch (allocation-free rule: __device__ globals)
__device__ float  g_xg[(size_t)SEQ * G4 * BATCH];  // [t][n][b], n = gate*H + j
__device__ __half g_h[2][BATCH * HID];             // [buf][b][k] fp16, k contiguous
// Producer-group flags: flag[bh][grp], grp = jg>>3 (8 CTAs x 8 epi-warps each).
// Consumer warp (domain bh, k-split kh) polls flag[bh][kh] >= 64*t.
__device__ unsigned int g_flag[16 * 32];           // one 128B line per flag

__device__ __forceinline__ float sigmoidf_(float x) {
    return 1.0f / (1.0f + __expf(-x));
}
__device__ __forceinline__ uint32_t f2tf32(float f) {
    uint32_t u;
    asm("cvt.rna.tf32.f32 %0, %1;" : "=r"(u) : "f"(f));
    return u;
}
__device__ __forceinline__ void mma_tf32(float& d0, float& d1, float& d2, float& d3,
                                         uint32_t a0, uint32_t a1, uint32_t a2, uint32_t a3,
                                         uint32_t b0, uint32_t b1) {
    asm volatile("mma.sync.aligned.m16n8k8.row.col.f32.tf32.tf32.f32 "
                 "{%0,%1,%2,%3}, {%4,%5,%6,%7}, {%8,%9}, {%0,%1,%2,%3};"
                 : "+f"(d0), "+f"(d1), "+f"(d2), "+f"(d3)
                 : "r"(a0), "r"(a1), "r"(a2), "r"(a3), "r"(b0), "r"(b1));
}
__device__ __forceinline__ void mma_f16(float& d0, float& d1, float& d2, float& d3,
                                        uint32_t a0, uint32_t a1, uint32_t a2, uint32_t a3,
                                        uint32_t b0, uint32_t b1) {
    asm volatile("mma.sync.aligned.m16n8k16.row.col.f32.f16.f16.f32 "
                 "{%0,%1,%2,%3}, {%4,%5,%6,%7}, {%8,%9}, {%0,%1,%2,%3};"
                 : "+f"(d0), "+f"(d1), "+f"(d2), "+f"(d3)
                 : "r"(a0), "r"(a1), "r"(a2), "r"(a3), "r"(b0), "r"(b1));
}
__device__ __forceinline__ uint32_t ldcg32(const void* p) {
    uint32_t v;
    asm volatile("ld.global.cg.u32 %0, [%1];" : "=r"(v) : "l"(p) : "memory");
    return v;
}
__device__ __forceinline__ uint32_t packh2(float a, float b) {
    __half2 h = __floats2half2_rn(a, b);
    return *(uint32_t*)&h;
}

__global__ void init_state() {
    int i = blockIdx.x * blockDim.x + threadIdx.x;   // 32768
    ((uint32_t*)g_h)[i] = 0u;                        // zero both fp16 h buffers
    if (i < 16 * 32) g_flag[i] = 0u;
}

// ============================================================================
// xg_gemm (tf32 mma, R8-proven): xg[t][n][b] = emb[tok] @ W_ih^T + bias
// ============================================================================
__global__ void __launch_bounds__(256)
xg_gemm(const int* __restrict__ x, const float* __restrict__ emb,
        const float* __restrict__ W_ih,
        const float* __restrict__ b_ih, const float* __restrict__ b_hh) {
    __shared__ float As[32][HPAD];
    __shared__ float Bs[32][HPAD];
    __shared__ int   tok_s[64];
    __shared__ float sbias[64];

    const int t    = blockIdx.y;
    const int ncta = blockIdx.x * 64;
    const int tid  = threadIdx.x;
    const int warp = tid >> 5;
    const int lane = tid & 31;
    const int gid  = lane >> 2;
    const int tig  = lane & 3;
    const int wm   = warp & 3;
    const int wn   = warp >> 2;
    const int m0   = wm * 16;

    if (tid < 64) {
        tok_s[tid] = x[tid * SEQ + t];
        int n = ncta + tid;
        sbias[tid] = b_ih[n] + b_hh[n];
    }
    __syncthreads();

    const uint32_t* Asu = (const uint32_t*)As;
    const uint32_t* Bsu = (const uint32_t*)Bs;

    float d[4][4] = {};

    for (int kt = 0; kt < EMB; kt += 32) {
        #pragma unroll
        for (int jj = 0; jj < 2; jj++) {
            int idx = tid + jj * 256;
            int row = idx >> 3, qk = idx & 7;
            float4 av = *(const float4*)(emb + (size_t)tok_s[row] * EMB + kt + qk * 4);
            As[qk*4+0][row] = __uint_as_float(f2tf32(av.x));
            As[qk*4+1][row] = __uint_as_float(f2tf32(av.y));
            As[qk*4+2][row] = __uint_as_float(f2tf32(av.z));
            As[qk*4+3][row] = __uint_as_float(f2tf32(av.w));
            float4 bv = *(const float4*)(W_ih + (size_t)(ncta + row) * EMB + kt + qk * 4);
            Bs[qk*4+0][row] = __uint_as_float(f2tf32(bv.x));
            Bs[qk*4+1][row] = __uint_as_float(f2tf32(bv.y));
            Bs[qk*4+2][row] = __uint_as_float(f2tf32(bv.z));
            Bs[qk*4+3][row] = __uint_as_float(f2tf32(bv.w));
        }
        __syncthreads();

        #pragma unroll
        for (int s = 0; s < 4; s++) {
            const int k0 = s * 8;
            uint32_t a0 = Asu[(k0 + tig)     * HPAD + m0 + gid];
            uint32_t a1 = Asu[(k0 + tig)     * HPAD + m0 + gid + 8];
            uint32_t a2 = Asu[(k0 + tig + 4) * HPAD + m0 + gid];
            uint32_t a3 = Asu[(k0 + tig + 4) * HPAD + m0 + gid + 8];
            #pragma unroll
            for (int nt = 0; nt < 4; nt++) {
                const int n0 = wn * 32 + nt * 8;
                uint32_t b0 = Bsu[(k0 + tig)     * HPAD + n0 + gid];
                uint32_t b1 = Bsu[(k0 + tig + 4) * HPAD + n0 + gid];
                mma_tf32(d[nt][0], d[nt][1], d[nt][2], d[nt][3],
                         a0, a1, a2, a3, b0, b1);
            }
        }
        __syncthreads();
    }

    #pragma unroll
    for (int nt = 0; nt < 4; nt++) {
        const int na = wn * 32 + nt * 8 + 2 * tig;
        const int nb = na + 1;
        const int r0 = m0 + gid;
        const int r1 = r0 + 8;
        g_xg[((size_t)t * G4 + ncta + na) * BATCH + r0] = d[nt][0] + sbias[na];
        g_xg[((size_t)t * G4 + ncta + nb) * BATCH + r0] = d[nt][1] + sbias[nb];
        g_xg[((size_t)t * G4 + ncta + na) * BATCH + r1] = d[nt][2] + sbias[na];
        g_xg[((size_t)t * G4 + ncta + nb) * BATCH + r1] = d[nt][3] + sbias[nb];
    }
}

// ============================================================================
// Persistent recurrence, fp16 mma m16n8k16 + fp32 accum, W-in-registers,
// DIRECT-LDG fragments (no smem h staging, no copy barrier).
// 128 CTAs x 512 threads. CTA = (j-group of 8 units, batch-half of 32).
// Warp = wm(2 m-tiles of 16 batches) x kh(8 k-splits of 64).
// Per step: poll own flag, front-batch 16 LDG.32 A-frags from L2, 16 mma,
// split-K partials in smem, epilogue, per-epilogue-warp flag release.
// ============================================================================
__global__ void __launch_bounds__(512, 1)
lstm_persistent(const float* __restrict__ W_hh) {
    extern __shared__ float sm[];
    float* pre = sm;                     // [8*32][PS] fp32 split-K partials

    const int tid  = threadIdx.x;        // 512
    const int cta  = blockIdx.x;
    const int jg   = cta >> 1;           // j-group 0..63
    const int bh   = cta & 1;            // batch half == flag domain
    const int warp = tid >> 5;
    const int lane = tid & 31;
    const int gid  = lane >> 2;
    const int tig  = lane & 3;
    const int wm   = warp & 1;           // m-tile: m0 = wm*16 (local batch)
    const int kh   = warp >> 1;          // k-split 0..7 (64 k each)
    const int m0   = wm * 16;
    const int j0   = jg * UNITS;
    const int b0g  = bh * 32;

    // Flags: consumer (this warp's k-range producers), producer (this CTA's group).
    unsigned int* my_cons_flag = &g_flag[(bh * 8 + kh) * 32];
    unsigned int* my_prod_flag = &g_flag[(bh * 8 + (jg >> 3)) * 32];

    // One-time: W fragments (fp16) -> registers. wreg[nt][ks16][2]:
    // n = nt*8+gid, k16-block ks16 within this warp's kh*64 range.
    // b0 covers k = 2tig,2tig+1; b1 covers k = 2tig+8,2tig+9 (within block).
    uint32_t wreg[4][4][2];
    #pragma unroll
    for (int nt = 0; nt < 4; nt++) {
        const int nn = nt * 8 + gid;
        const int g = nn >> 3, u = nn & 7;
        const float* wrow = W_hh + (size_t)(g * HID + j0 + u) * HID + kh * 64;
        #pragma unroll
        for (int ks = 0; ks < 4; ks++) {
            const int k0 = ks * 16 + 2 * tig;
            wreg[nt][ks][0] = packh2(wrow[k0],     wrow[k0 + 1]);
            wreg[nt][ks][1] = packh2(wrow[k0 + 8], wrow[k0 + 9]);
        }
    }
    float c_reg = 0.0f;

    // epilogue identity (tid<256): local batch (lane), unit (warp)
    const int ebl = tid & 31;
    const int eu  = (tid >> 5) & 7;
    const int ebg = b0g + ebl;

    // A-frag base offsets (halves): rows = global batch, cols = k.
    const int rA0 = (b0g + m0 + gid) * HID;       // row gid
    const int rA1 = (b0g + m0 + gid + 8) * HID;   // row gid+8

    for (int t = 0; t < SEQ; t++) {
        const int rb = t & 1;
        const __half* hb = g_h[rb];

        // Dataflow wait: this warp's producer group finished step t-1.
        if (t > 0) {
            const unsigned tgt = 64u * (unsigned)t;
            unsigned v;
            do {
                asm volatile("ld.acquire.gpu.global.u32 %0, [%1];"
                             : "=r"(v) : "l"(my_cons_flag) : "memory");
            } while (v < tgt);
        }

        // Prefetch xg (epilogue threads) — overlaps the fragment loads.
        float xi = 0.f, xf = 0.f, xG = 0.f, xo = 0.f;
        if (tid < 256) {
            const float* xg = g_xg + ((size_t)t * G4 + j0 + eu) * BATCH + ebg;
            xi = __ldcg(xg + 0 * HID * BATCH);
            xf = __ldcg(xg + 1 * HID * BATCH);
            xG = __ldcg(xg + 2 * HID * BATCH);
            xo = __ldcg(xg + 3 * HID * BATCH);
        }

        // Front-batch all 16 A-fragment LDGs (MLP=16, L2-direct).
        uint32_t aa[4][4];
        #pragma unroll
        for (int ks = 0; ks < 4; ks++) {
            const int k0 = kh * 64 + ks * 16 + 2 * tig;
            aa[ks][0] = ldcg32(hb + rA0 + k0);
            aa[ks][1] = ldcg32(hb + rA1 + k0);
            aa[ks][2] = ldcg32(hb + rA0 + k0 + 8);
            aa[ks][3] = ldcg32(hb + rA1 + k0 + 8);
        }

        float d[4][4] = {};
        #pragma unroll
        for (int ks = 0; ks < 4; ks++) {
            #pragma unroll
            for (int nt = 0; nt < 4; nt++) {
                mma_f16(d[nt][0], d[nt][1], d[nt][2], d[nt][3],
                        aa[ks][0], aa[ks][1], aa[ks][2], aa[ks][3],
                        wreg[nt][ks][0], wreg[nt][ks][1]);
            }
        }

        // Split-K partials: pre[kh*32 + n][local m].
        #pragma unroll
        for (int nt = 0; nt < 4; nt++) {
            const int na = nt * 8 + 2 * tig;
            const int r0 = m0 + gid;
            pre[(kh * 32 + na)     * PS + r0]     = d[nt][0];
            pre[(kh * 32 + na + 1) * PS + r0]     = d[nt][1];
            pre[(kh * 32 + na)     * PS + r0 + 8] = d[nt][2];
            pre[(kh * 32 + na + 1) * PS + r0 + 8] = d[nt][3];
        }
        __syncthreads();   // join: all warps' mma reads + partials complete

        if (tid < 256) {
            const int b = ebl, u = eu;
            float ai = 0.f, af = 0.f, ag = 0.f, ao = 0.f;
            #pragma unroll
            for (int q = 0; q < 8; q++) {
                ai += pre[(q * 32 + 0 * 8 + u) * PS + b];
                af += pre[(q * 32 + 1 * 8 + u) * PS + b];
                ag += pre[(q * 32 + 2 * 8 + u) * PS + b];
                ao += pre[(q * 32 + 3 * 8 + u) * PS + b];
            }

            float gi = sigmoidf_(ai + xi);
            float gf = sigmoidf_(af + xf);
            float gG = tanhf   (ag + xG);
            float go = sigmoidf_(ao + xo);
            c_reg = gf * c_reg + gi * gG;
            float hv = go * tanhf(c_reg);

            // Store h (fp16, [b][k] layout).
            __half hh = __float2half_rn(hv);
            unsigned short hbits = *(unsigned short*)&hh;
            asm volatile("st.global.cg.b16 [%0], %1;"
                         :: "l"(&g_h[rb ^ 1][(size_t)ebg * HID + j0 + eu]), "h"(hbits)
                         : "memory");

            // Per-epilogue-warp release: this warp's unit row is published.
            if (t < SEQ - 1) {
                __syncwarp();
                if (lane == 0) {
                    __threadfence();
                    asm volatile("red.release.gpu.global.add.u32 [%0], 1;"
                                 :: "l"(my_prod_flag) : "memory");
                }
            }
        }

        __syncthreads();   // protect pre reuse next step
    }
}

// Final FC: warp per output element. h fp16 [b][k]; final h in g_h[0].
__global__ void fc_kernel(const float* __restrict__ W_fc, const float* __restrict__ b_fc,
                          float* __restrict__ out) {
    const int warp = (blockIdx.x * blockDim.x + threadIdx.x) >> 5;
    const int lane = threadIdx.x & 31;
    const int b = warp >> 2, c = warp & 3;
    const __half* h0 = g_h[0] + (size_t)b * HID;
    const float* w  = W_fc + c * HID;
    float acc = 0.f;
    #pragma unroll 4
    for (int k = lane; k < HID; k += 32)
        acc += __half2float(h0[k]) * w[k];
    #pragma unroll
    for (int off = 16; off; off >>= 1)
        acc += __shfl_xor_sync(0xFFFFFFFFu, acc, off);
    if (lane == 0) out[b * NCLS + c] = acc + b_fc[c];
}

extern "C" void kernel_launch(void* const* d_in, const int* in_sizes, int n_in,
                              void* d_out, int out_size) {
    const int*   x    = (const int*)  d_in[0];
    const float* emb  = (const float*)d_in[1];
    const float* W_ih = (const float*)d_in[2];
    const float* W_hh = (const float*)d_in[3];
    const float* b_ih = (const float*)d_in[4];
    const float* b_hh = (const float*)d_in[5];
    const float* W_fc = (const float*)d_in[6];
    const float* b_fc = (const float*)d_in[7];
    float* out = (float*)d_out;

    const int smem_bytes = 8 * 32 * PS * sizeof(float);   // 36 KiB
    cudaFuncSetAttribute(lstm_persistent,
                         cudaFuncAttributeMaxDynamicSharedMemorySize, smem_bytes);

    init_state<<<64, 512>>>();

    dim3 g1(G4 / 64, SEQ);   // 32 x 512 CTAs
    xg_gemm<<<g1, 256>>>(x, emb, W_ih, b_ih, b_hh);

    lstm_persistent<<<NCTA, 512, smem_bytes>>>(W_hh);

    fc_kernel<<<32, 256>>>(W_fc, b_fc, out);
}

// round 16
// speedup vs baseline: 1.1281x; 1.1281x over previous
#include <cuda_runtime.h>
#include <math.h>
#include <stdint.h>

#define BATCH 64
#define SEQ   512
#define EMB   256
#define HID   512
#define G4    2048   // 4*HID
#define NCLS  4
#define NCTA  128    // persistent CTAs: 64 j-groups x 2 batch-halves
#define UNITS 8      // hidden units per j-group
#define HPAD  68     // fp32 pad stride (xg_gemm)
#define HS    40     // h_s row stride (32 batch + 8 pad) -> conflict-free frags
#define PS    36     // pre row stride (32 + 4)
#define PREN  (8 * 32 * PS)   // one pre buffer (floats)

// Scratch (allocation-free rule: __device__ globals)
__device__ float g_xg[(size_t)SEQ * G4 * BATCH];   // [t][n][b], n = gate*H + j
__device__ float g_h[2][HID * BATCH];              // [buf][k][b], tf32-bit floats
// Producer-group flags: flag[bh][grp], grp = jg>>3 (8 producer CTAs each).
// Consumer warp (domain bh, k-split kh) polls flag[bh][kh] >= 8*t.
__device__ unsigned int g_flag[16 * 32];           // one 128B line per flag

__device__ __forceinline__ float sigmoidf_(float x) {
    return 1.0f / (1.0f + __expf(-x));
}
__device__ __forceinline__ uint32_t f2tf32(float f) {
    uint32_t u;
    asm("cvt.rna.tf32.f32 %0, %1;" : "=r"(u) : "f"(f));
    return u;
}
__device__ __forceinline__ void mma_tf32(float& d0, float& d1, float& d2, float& d3,
                                         uint32_t a0, uint32_t a1, uint32_t a2, uint32_t a3,
                                         uint32_t b0, uint32_t b1) {
    asm volatile("mma.sync.aligned.m16n8k8.row.col.f32.tf32.tf32.f32 "
                 "{%0,%1,%2,%3}, {%4,%5,%6,%7}, {%8,%9}, {%0,%1,%2,%3};"
                 : "+f"(d0), "+f"(d1), "+f"(d2), "+f"(d3)
                 : "r"(a0), "r"(a1), "r"(a2), "r"(a3), "r"(b0), "r"(b1));
}

// cp.async.cg: 16B global->shared, L1-bypass.
__device__ __forceinline__ void cp_async16(void* smem_dst, const void* gmem_src) {
    unsigned saddr = (unsigned)__cvta_generic_to_shared(smem_dst);
    asm volatile("cp.async.cg.shared.global [%0], [%1], 16;"
                 :: "r"(saddr), "l"(gmem_src) : "memory");
}
__device__ __forceinline__ void cp_async_commit() {
    asm volatile("cp.async.commit_group;" ::: "memory");
}
template <int N>
__device__ __forceinline__ void cp_async_wait() {
    asm volatile("cp.async.wait_group %0;" :: "n"(N) : "memory");
}

__global__ void init_state() {
    int i = blockIdx.x * blockDim.x + threadIdx.x;
    g_h[0][i] = 0.0f;
    if (i < 16 * 32) g_flag[i] = 0u;
}

// ============================================================================
// xg_gemm (tf32 mma, R8-proven): xg[t][n][b] = emb[tok] @ W_ih^T + bias
// ============================================================================
__global__ void __launch_bounds__(256)
xg_gemm(const int* __restrict__ x, const float* __restrict__ emb,
        const float* __restrict__ W_ih,
        const float* __restrict__ b_ih, const float* __restrict__ b_hh) {
    __shared__ float As[32][HPAD];
    __shared__ float Bs[32][HPAD];
    __shared__ int   tok_s[64];
    __shared__ float sbias[64];

    const int t    = blockIdx.y;
    const int ncta = blockIdx.x * 64;
    const int tid  = threadIdx.x;
    const int warp = tid >> 5;
    const int lane = tid & 31;
    const int gid  = lane >> 2;
    const int tig  = lane & 3;
    const int wm   = warp & 3;
    const int wn   = warp >> 2;
    const int m0   = wm * 16;

    if (tid < 64) {
        tok_s[tid] = x[tid * SEQ + t];
        int n = ncta + tid;
        sbias[tid] = b_ih[n] + b_hh[n];
    }
    __syncthreads();

    const uint32_t* Asu = (const uint32_t*)As;
    const uint32_t* Bsu = (const uint32_t*)Bs;

    float d[4][4] = {};

    for (int kt = 0; kt < EMB; kt += 32) {
        #pragma unroll
        for (int jj = 0; jj < 2; jj++) {
            int idx = tid + jj * 256;
            int row = idx >> 3, qk = idx & 7;
            float4 av = *(const float4*)(emb + (size_t)tok_s[row] * EMB + kt + qk * 4);
            As[qk*4+0][row] = __uint_as_float(f2tf32(av.x));
            As[qk*4+1][row] = __uint_as_float(f2tf32(av.y));
            As[qk*4+2][row] = __uint_as_float(f2tf32(av.z));
            As[qk*4+3][row] = __uint_as_float(f2tf32(av.w));
            float4 bv = *(const float4*)(W_ih + (size_t)(ncta + row) * EMB + kt + qk * 4);
            Bs[qk*4+0][row] = __uint_as_float(f2tf32(bv.x));
            Bs[qk*4+1][row] = __uint_as_float(f2tf32(bv.y));
            Bs[qk*4+2][row] = __uint_as_float(f2tf32(bv.z));
            Bs[qk*4+3][row] = __uint_as_float(f2tf32(bv.w));
        }
        __syncthreads();

        #pragma unroll
        for (int s = 0; s < 4; s++) {
            const int k0 = s * 8;
            uint32_t a0 = Asu[(k0 + tig)     * HPAD + m0 + gid];
            uint32_t a1 = Asu[(k0 + tig)     * HPAD + m0 + gid + 8];
            uint32_t a2 = Asu[(k0 + tig + 4) * HPAD + m0 + gid];
            uint32_t a3 = Asu[(k0 + tig + 4) * HPAD + m0 + gid + 8];
            #pragma unroll
            for (int nt = 0; nt < 4; nt++) {
                const int n0 = wn * 32 + nt * 8;
                uint32_t b0 = Bsu[(k0 + tig)     * HPAD + n0 + gid];
                uint32_t b1 = Bsu[(k0 + tig + 4) * HPAD + n0 + gid];
                mma_tf32(d[nt][0], d[nt][1], d[nt][2], d[nt][3],
                         a0, a1, a2, a3, b0, b1);
            }
        }
        __syncthreads();
    }

    #pragma unroll
    for (int nt = 0; nt < 4; nt++) {
        const int na = wn * 32 + nt * 8 + 2 * tig;
        const int nb = na + 1;
        const int r0 = m0 + gid;
        const int r1 = r0 + 8;
        g_xg[((size_t)t * G4 + ncta + na) * BATCH + r0] = d[nt][0] + sbias[na];
        g_xg[((size_t)t * G4 + ncta + nb) * BATCH + r0] = d[nt][1] + sbias[nb];
        g_xg[((size_t)t * G4 + ncta + na) * BATCH + r1] = d[nt][2] + sbias[na];
        g_xg[((size_t)t * G4 + ncta + nb) * BATCH + r1] = d[nt][3] + sbias[nb];
    }
}

// ============================================================================
// Persistent recurrence, tf32 mma, W-in-registers, dataflow flags (R14 base).
// New in R16: warp-private copy tiles (no bar64 — __syncwarp only),
// double-buffered split-K 'pre' (one __syncthreads per step).
// ============================================================================
__global__ void __launch_bounds__(512, 1)
lstm_persistent(const float* __restrict__ W_hh) {
    extern __shared__ float sm[];
    float* h_s = sm;                     // [512][HS] tf32 bits (32 b + pad)
    float* pre = sm + HID * HS;          // [2][8*32][PS] fp32 split-K partials

    const int tid  = threadIdx.x;        // 512
    const int cta  = blockIdx.x;
    const int jg   = cta >> 1;           // j-group 0..63
    const int bh   = cta & 1;            // batch half == flag domain
    const int warp = tid >> 5;
    const int lane = tid & 31;
    const int gid  = lane >> 2;
    const int tig  = lane & 3;
    const int wm   = warp & 1;           // m-tile: m0 = wm*16 (local batch)
    const int kh   = warp >> 1;          // k-split 0..7 (64 k each)
    const int m0   = wm * 16;
    const int j0   = jg * UNITS;
    const int b0g  = bh * 32;

    // Flag addresses: this warp's consumer flag, this CTA's producer flag.
    unsigned int* my_cons_flag = &g_flag[(bh * 8 + kh) * 32];
    unsigned int* my_prod_flag = &g_flag[(bh * 8 + (jg >> 3)) * 32];

    // One-time: W fragments -> registers (64 regs), per warp's kh range.
    uint32_t wreg[4][8][2];
    #pragma unroll
    for (int nt = 0; nt < 4; nt++) {
        const int nn = nt * 8 + gid;
        const int g = nn >> 3, u = nn & 7;
        const float* wrow = W_hh + (size_t)(g * HID + j0 + u) * HID + kh * 64;
        #pragma unroll
        for (int ks = 0; ks < 8; ks++) {
            wreg[nt][ks][0] = f2tf32(wrow[ks * 8 + tig]);
            wreg[nt][ks][1] = f2tf32(wrow[ks * 8 + tig + 4]);
        }
    }
    float c_reg = 0.0f;

    const uint32_t* Hsu = (const uint32_t*)h_s;
    // epilogue identity (tid<256): local batch (lane), unit (warp)
    const int ebl = tid & 31;
    const int eu  = (tid >> 5) & 7;
    const int ebg = b0g + ebl;

    // Warp-private copy tile: 64 k-rows [kh*64, kh*64+64), 16 batch cols
    // [wm*16, wm*16+16). 64 rows x 4 x16B pieces = 256 pieces / 32 lanes = 8.
    const int krow0 = kh * 64;
    const int c0    = wm * 16;          // local batch col base

    for (int t = 0; t < SEQ; t++) {
        const int rb = t & 1;
        const float* hsrc = g_h[rb];
        float* preb = pre + (t & 1) * PREN;

        // Dataflow wait: this warp's producer group must have finished step t-1.
        if (t > 0) {
            const unsigned tgt = 8u * (unsigned)t;
            unsigned v;
            do {
                asm volatile("ld.acquire.gpu.global.u32 %0, [%1];"
                             : "=r"(v) : "l"(my_cons_flag) : "memory");
            } while (v < tgt);
        }

        // Per-warp private copy (no cross-warp sharing).
        #pragma unroll
        for (int i = 0; i < 8; i++) {
            int p = lane + i * 32;
            int row = krow0 + (p >> 2), sub = p & 3;
            cp_async16(h_s + row * HS + c0 + sub * 4,
                       hsrc + row * BATCH + b0g + c0 + sub * 4);
        }
        cp_async_commit();

        // Prefetch xg — overlaps the copy.
        float xi = 0.f, xf = 0.f, xG = 0.f, xo = 0.f;
        if (tid < 256) {
            const float* xg = g_xg + ((size_t)t * G4 + j0 + eu) * BATCH + ebg;
            xi = __ldcg(xg + 0 * HID * BATCH);
            xf = __ldcg(xg + 1 * HID * BATCH);
            xG = __ldcg(xg + 2 * HID * BATCH);
            xo = __ldcg(xg + 3 * HID * BATCH);
        }

        cp_async_wait<0>();
        __syncwarp();   // intra-warp visibility of cp.async smem writes

        float d[4][4] = {};
        #pragma unroll
        for (int ks = 0; ks < 8; ks++) {
            const int k0 = kh * 64 + ks * 8;
            uint32_t a0 = Hsu[(k0 + tig)     * HS + m0 + gid];
            uint32_t a1 = Hsu[(k0 + tig)     * HS + m0 + gid + 8];
            uint32_t a2 = Hsu[(k0 + tig + 4) * HS + m0 + gid];
            uint32_t a3 = Hsu[(k0 + tig + 4) * HS + m0 + gid + 8];
            #pragma unroll
            for (int nt = 0; nt < 4; nt++) {
                mma_tf32(d[nt][0], d[nt][1], d[nt][2], d[nt][3],
                         a0, a1, a2, a3, wreg[nt][ks][0], wreg[nt][ks][1]);
            }
        }

        // Split-K partials: preb[kh*32 + n][local m].
        #pragma unroll
        for (int nt = 0; nt < 4; nt++) {
            const int na = nt * 8 + 2 * tig;
            const int r0 = m0 + gid;
            preb[(kh * 32 + na)     * PS + r0]     = d[nt][0];
            preb[(kh * 32 + na + 1) * PS + r0]     = d[nt][1];
            preb[(kh * 32 + na)     * PS + r0 + 8] = d[nt][2];
            preb[(kh * 32 + na + 1) * PS + r0 + 8] = d[nt][3];
        }
        __syncthreads();   // single join per step (pre double-buffered)

        if (tid < 256) {
            const int b = ebl, u = eu;
            float ai = 0.f, af = 0.f, ag = 0.f, ao = 0.f;
            #pragma unroll
            for (int q = 0; q < 8; q++) {
                ai += preb[(q * 32 + 0 * 8 + u) * PS + b];
                af += preb[(q * 32 + 1 * 8 + u) * PS + b];
                ag += preb[(q * 32 + 2 * 8 + u) * PS + b];
                ao += preb[(q * 32 + 3 * 8 + u) * PS + b];
            }

            float gi = sigmoidf_(ai + xi);
            float gf = sigmoidf_(af + xf);
            float gG = tanhf   (ag + xG);
            float go = sigmoidf_(ao + xo);
            c_reg = gf * c_reg + gi * gG;
            float hv = go * tanhf(c_reg);

            __stcg(&g_h[rb ^ 1][(j0 + u) * BATCH + ebg],
                   __uint_as_float(f2tf32(hv)));
        }

        // Producer arrive: this CTA's 8 h rows for t+1 are published.
        // Epilogue threads store h; tid0 is an epilogue thread's warp leader —
        // need all 8 epilogue warps done: they all pass the NEXT flag wait only
        // after producers release, and our release must cover all 256 epilogue
        // threads. Use a second syncthreads-free join: epilogue warps signal via
        // bar.arrive pattern is overkill — keep tid0 release after __syncthreads
        // of NEXT loop iteration is too late; instead do a light named barrier
        // joining only the 8 epilogue warps, then tid0 releases.
        if (t < SEQ - 1) {
            if (tid < 256) {
                asm volatile("bar.sync 15, 256;" ::: "memory");
                if (tid == 0) {
                    __threadfence();
                    asm volatile("red.release.gpu.global.add.u32 [%0], 1;"
                                 :: "l"(my_prod_flag) : "memory");
                }
            }
        }
    }
}

// Final FC: warp per output element (64*4 = 256 warps = 32 blocks).
__global__ void fc_kernel(const float* __restrict__ W_fc, const float* __restrict__ b_fc,
                          float* __restrict__ out) {
    const int warp = (blockIdx.x * blockDim.x + threadIdx.x) >> 5;
    const int lane = threadIdx.x & 31;
    const int b = warp >> 2, c = warp & 3;
    const float* h0 = g_h[0];
    const float* w  = W_fc + c * HID;
    float acc = 0.f;
    #pragma unroll 4
    for (int k = lane; k < HID; k += 32)
        acc += h0[k * BATCH + b] * w[k];
    #pragma unroll
    for (int off = 16; off; off >>= 1)
        acc += __shfl_xor_sync(0xFFFFFFFFu, acc, off);
    if (lane == 0) out[b * NCLS + c] = acc + b_fc[c];
}

extern "C" void kernel_launch(void* const* d_in, const int* in_sizes, int n_in,
                              void* d_out, int out_size) {
    const int*   x    = (const int*)  d_in[0];
    const float* emb  = (const float*)d_in[1];
    const float* W_ih = (const float*)d_in[2];
    const float* W_hh = (const float*)d_in[3];
    const float* b_ih = (const float*)d_in[4];
    const float* b_hh = (const float*)d_in[5];
    const float* W_fc = (const float*)d_in[6];
    const float* b_fc = (const float*)d_in[7];
    float* out = (float*)d_out;

    const int smem_bytes = (HID * HS + 2 * PREN) * sizeof(float);   // ~152 KiB
    cudaFuncSetAttribute(lstm_persistent,
                         cudaFuncAttributeMaxDynamicSharedMemorySize, smem_bytes);

    init_state<<<64, 512>>>();

    dim3 g1(G4 / 64, SEQ);   // 32 x 512 CTAs
    xg_gemm<<<g1, 256>>>(x, emb, W_ih, b_ih, b_hh);

    lstm_persistent<<<NCTA, 512, smem_bytes>>>(W_hh);

    fc_kernel<<<32, 256>>>(W_fc, b_fc, out);
}